// round 7
// baseline (speedup 1.0000x reference)
#include <cuda_runtime.h>

#define NN   10000
#define NE   160000
#define NCH  16
#define CQ   80        // c*5+q
#define OPD  80        // o*5+p
#define NFR  10        // f*2+r
#define KTOT 800       // cq*10+fr
#define TE   128       // edges per block in edge GEMM

// scratch (device globals: allocation-free). __align__(16) is load-bearing:
// these are read via LDG.128 (float4).
__device__ __align__(16) float g_y1[NN * OPD];
__device__ __align__(16) float g_h [NN * OPD];
__device__ __align__(16) float g_y2[NN * OPD];
__device__ __align__(16) float g_Wt1 [KTOT * OPD];  // [k][n] k=cq*10+fr, n=o*5+p
__device__ __align__(16) float g_Wt2 [KTOT * OPD];
__device__ __align__(16) float g_Wst1[CQ * OPD];    // [cq][op]
__device__ __align__(16) float g_Wst2[CQ * OPD];

#define SMEM_EDGE (((CQ*TE) + (TE*NFR) + (80*80)) * 4 + TE * 4)

// ---- f32x2 packed helpers (ptxas never auto-emits FFMA2; PTX-only path) ----
static __device__ __forceinline__ unsigned long long pk2(float a, float b) {
    unsigned long long r;
    asm("mov.b64 %0, {%1,%2};" : "=l"(r) : "f"(a), "f"(b));
    return r;
}
static __device__ __forceinline__ void fma2(unsigned long long& d,
                                            unsigned long long a,
                                            unsigned long long b) {
    asm("fma.rn.f32x2 %0, %1, %2, %0;" : "+l"(d) : "l"(a), "l"(b));
}
static __device__ __forceinline__ float2 upk2(unsigned long long v) {
    float2 r;
    asm("mov.b64 {%0,%1}, %2;" : "=f"(r.x), "=f"(r.y) : "l"(v));
    return r;
}

// ---- weight re-layout: W[o,c,p,q,f,r] -> Wt[k=cq*10+fr][n=o*5+p]; Ws -> Wst[cq][op]
__global__ void prep_weights(const float* __restrict__ W1, const float* __restrict__ W2,
                             const float* __restrict__ Ws1, const float* __restrict__ Ws2) {
    int i = blockIdx.x * blockDim.x + threadIdx.x;
    if (i < KTOT * OPD) {
        int n = i % OPD, k = i / OPD;
        int o = n / 5, p = n % 5;
        int fr = k % NFR, cq = k / NFR;
        int c = cq / 5, q = cq % 5;
        int f = fr >> 1, r = fr & 1;
        int src = ((((o * NCH + c) * 5 + p) * 5 + q) * 5 + f) * 2 + r;
        g_Wt1[i] = W1[src];
        g_Wt2[i] = W2[src];
    }
    if (i < CQ * OPD) {
        int op = i % OPD, cq = i / OPD;
        int o = op / 5, p = op % 5, c = cq / 5, q = cq % 5;
        int src = ((o * NCH + c) * 5 + p) * 5 + q;
        g_Wst1[i] = Ws1[src];
        g_Wst2[i] = Ws2[src];
    }
}

// ---- self-interaction: y[n,op] = sum_cq x[n,cq]*Wst[cq,op] + b[o]*(p==0)
// 4 nodes per block, 80 threads (one per op). Initializes y fully (no pre-zero needed).
__global__ __launch_bounds__(80) void self_gemm(const float* __restrict__ x,
                                                const float* __restrict__ Wst,
                                                const float* __restrict__ b,
                                                float* __restrict__ y) {
    __shared__ float xs[4][CQ];
    int n0 = blockIdx.x * 4;
    int t = threadIdx.x;  // op
#pragma unroll
    for (int j = 0; j < 4; ++j) xs[j][t] = x[(n0 + j) * CQ + t];
    __syncthreads();
    float bias = ((t % 5) == 0) ? b[t / 5] : 0.f;
    float a0 = bias, a1 = bias, a2 = bias, a3 = bias;
#pragma unroll 8
    for (int k = 0; k < CQ; ++k) {
        float w = __ldg(&Wst[k * OPD + t]);
        a0 = fmaf(xs[0][k], w, a0);
        a1 = fmaf(xs[1][k], w, a1);
        a2 = fmaf(xs[2][k], w, a2);
        a3 = fmaf(xs[3][k], w, a3);
    }
    y[(n0 + 0) * OPD + t] = a0;
    y[(n0 + 1) * OPD + t] = a1;
    y[(n0 + 2) * OPD + t] = a2;
    y[(n0 + 3) * OPD + t] = a3;
}

// ---- edge conv GEMM: for 128 edges, msg[e,n] = sum_k (xt[e,cq]*pre[e,fr]) * Wt[k,n]
// then atomicAdd into y[dst].
// Thread tile: 4 edges x 20 outputs (10 f32x2 pairs). 128 threads = 32 eg x 4 ng.
__global__ __launch_bounds__(128, 2) void edge_gemm(
    const float* __restrict__ xin,        // [NN, 80] source features
    const int* __restrict__ ei,           // [NE, 2] int32 (JAX default x64-disabled!)
    const float* __restrict__ precomp,    // [NE, 10]
    const float* __restrict__ conn,       // [NE]
    const float* __restrict__ Wt,         // [800, 80]
    float* __restrict__ y)                // [NN, 80] accumulate
{
    extern __shared__ float smem[];
    float* xt_s  = smem;                    // [80][TE]
    float* pre_s = xt_s + CQ * TE;          // [TE][10]
    float* W_s   = pre_s + TE * NFR;        // [80][80] K-tile
    int*   dst_s = (int*)(W_s + 80 * 80);   // [TE]

    const int tid = threadIdx.x;
    const int e0 = blockIdx.x * TE;

    // Phase 1: gather + parallel transport (thread <-> edge, 1:1)
    {
        int e = e0 + tid;
        int src = ei[2 * e];
        dst_s[tid] = ei[2 * e + 1];
        float phi = conn[e];
        float s1, c1, s2, c2;
        __sincosf(phi, &s1, &c1);
        __sincosf(2.f * phi, &s2, &c2);
        const float4* xr = (const float4*)(xin + (long long)src * CQ);
#pragma unroll
        for (int c4 = 0; c4 < 4; ++c4) {
            float v[20];
#pragma unroll
            for (int j = 0; j < 5; ++j) {
                float4 t4 = xr[c4 * 5 + j];
                v[4 * j + 0] = t4.x; v[4 * j + 1] = t4.y;
                v[4 * j + 2] = t4.z; v[4 * j + 3] = t4.w;
            }
#pragma unroll
            for (int cc = 0; cc < 4; ++cc) {
                int c = c4 * 4 + cc;
                float m0 = v[cc * 5 + 0];
                float x1 = v[cc * 5 + 1], x2 = v[cc * 5 + 2];
                float x3 = v[cc * 5 + 3], x4 = v[cc * 5 + 4];
                xt_s[(c * 5 + 0) * TE + tid] = m0;
                xt_s[(c * 5 + 1) * TE + tid] = c1 * x1 - s1 * x2;
                xt_s[(c * 5 + 2) * TE + tid] = s1 * x1 + c1 * x2;
                xt_s[(c * 5 + 3) * TE + tid] = c2 * x3 - s2 * x4;
                xt_s[(c * 5 + 4) * TE + tid] = s2 * x3 + c2 * x4;
            }
        }
    }
    // stage precomp coalesced
    for (int i = tid; i < TE * NFR; i += TE)
        pre_s[i] = precomp[(long long)e0 * NFR + i];
    __syncthreads();

    const int ng = tid & 3;    // 4 n-groups of 20
    const int eg = tid >> 2;   // 32 edge-groups of 4
    const int nb = ng * 20;
    const int eb = eg * 4;

    // pre held in registers: the rank-1 trick that keeps us under LDS bandwidth
    float pre_r[4][NFR];
#pragma unroll
    for (int i = 0; i < 4; ++i)
#pragma unroll
        for (int f = 0; f < NFR; ++f)
            pre_r[i][f] = pre_s[(eb + i) * NFR + f];

    unsigned long long acc[4][10];
#pragma unroll
    for (int i = 0; i < 4; ++i)
#pragma unroll
        for (int j = 0; j < 10; ++j) acc[i][j] = 0ULL;

#pragma unroll 1
    for (int kt = 0; kt < 10; ++kt) {
        if (kt) __syncthreads();
        // load W K-tile (contiguous 6400 floats, coalesced float4)
        {
            const float4* wsrc = (const float4*)(Wt + kt * 80 * 80);
            float4* wdst = (float4*)W_s;
            for (int i = tid; i < 1600; i += TE) wdst[i] = wsrc[i];
        }
        __syncthreads();
#pragma unroll 1
        for (int cql = 0; cql < 8; ++cql) {
            float4 xt4 = *(const float4*)&xt_s[(kt * 8 + cql) * TE + eb];
            float xtv[4] = {xt4.x, xt4.y, xt4.z, xt4.w};
#pragma unroll
            for (int fr = 0; fr < NFR; ++fr) {
                unsigned long long a2[4];
#pragma unroll
                for (int i = 0; i < 4; ++i) {
                    float a = xtv[i] * pre_r[i][fr];
                    a2[i] = pk2(a, a);
                }
                const unsigned long long* wrow =
                    (const unsigned long long*)(W_s + (cql * 10 + fr) * 80 + nb);
#pragma unroll
                for (int j = 0; j < 10; ++j) {
                    unsigned long long w2 = wrow[j];
                    fma2(acc[0][j], a2[0], w2);
                    fma2(acc[1][j], a2[1], w2);
                    fma2(acc[2][j], a2[2], w2);
                    fma2(acc[3][j], a2[3], w2);
                }
            }
        }
    }

    // Epilogue: scatter-add to destination nodes
#pragma unroll
    for (int i = 0; i < 4; ++i) {
        int d = dst_s[eb + i];
        float* yr = y + (long long)d * OPD + nb;
#pragma unroll
        for (int j = 0; j < 10; ++j) {
            float2 v = upk2(acc[i][j]);
            atomicAdd(yr + 2 * j,     v.x);
            atomicAdd(yr + 2 * j + 1, v.y);
        }
    }
}

// ---- Fourier -> samples -> ReLU -> Fourier (K=7 samples, order 2), optional residual
__global__ void nonlin_kernel(const float* __restrict__ in,
                              const float* __restrict__ resid,
                              float* __restrict__ out) {
    int i = blockIdx.x * blockDim.x + threadIdx.x;  // (node, channel)
    if (i >= NN * NCH) return;
    float v0 = in[i * 5 + 0], v1 = in[i * 5 + 1], v2 = in[i * 5 + 2];
    float v3 = in[i * 5 + 3], v4 = in[i * 5 + 4];
    if (resid) {
        v0 += resid[i * 5 + 0]; v1 += resid[i * 5 + 1]; v2 += resid[i * 5 + 2];
        v3 += resid[i * 5 + 3]; v4 += resid[i * 5 + 4];
    }
    float o0 = 0.f, o1 = 0.f, o2 = 0.f, o3 = 0.f, o4 = 0.f;
#pragma unroll
    for (int k = 0; k < 7; ++k) {
        float th = 0.8975979010256552f * (float)k;  // 2*pi/7 * k
        float s1, c1, s2, c2;
        __sincosf(th, &s1, &c1);
        __sincosf(2.f * th, &s2, &c2);
        float s = v0 + c1 * v1 + s1 * v2 + c2 * v3 + s2 * v4;
        s = fmaxf(s, 0.f);
        o0 += s;
        o1 += s * c1; o2 += s * s1;
        o3 += s * c2; o4 += s * s2;
    }
    out[i * 5 + 0] = o0 * (1.f / 7.f);
    out[i * 5 + 1] = o1 * (2.f / 7.f);
    out[i * 5 + 2] = o2 * (2.f / 7.f);
    out[i * 5 + 3] = o3 * (2.f / 7.f);
    out[i * 5 + 4] = o4 * (2.f / 7.f);
}

extern "C" void kernel_launch(void* const* d_in, const int* in_sizes, int n_in,
                              void* d_out, int out_size) {
    const float* x    = (const float*)d_in[0];
    const int*   ei   = (const int*)d_in[1];   // int32: JAX demotes int64 by default
    const float* pre  = (const float*)d_in[2];
    const float* conn = (const float*)d_in[3];
    const float* W1   = (const float*)d_in[4];
    const float* b1   = (const float*)d_in[5];
    const float* Ws1  = (const float*)d_in[6];
    const float* W2   = (const float*)d_in[7];
    const float* b2   = (const float*)d_in[8];
    const float* Ws2  = (const float*)d_in[9];
    float* out = (float*)d_out;

    cudaFuncSetAttribute(edge_gemm, cudaFuncAttributeMaxDynamicSharedMemorySize, SMEM_EDGE);

    float *y1, *h, *y2, *Wt1, *Wt2, *Wst1, *Wst2;
    cudaGetSymbolAddress((void**)&y1,   g_y1);
    cudaGetSymbolAddress((void**)&h,    g_h);
    cudaGetSymbolAddress((void**)&y2,   g_y2);
    cudaGetSymbolAddress((void**)&Wt1,  g_Wt1);
    cudaGetSymbolAddress((void**)&Wt2,  g_Wt2);
    cudaGetSymbolAddress((void**)&Wst1, g_Wst1);
    cudaGetSymbolAddress((void**)&Wst2, g_Wst2);

    prep_weights<<<(KTOT * OPD + 255) / 256, 256>>>(W1, W2, Ws1, Ws2);

    // layer 1
    self_gemm<<<NN / 4, 80>>>(x, Wst1, b1, y1);
    edge_gemm<<<NE / TE, TE, SMEM_EDGE>>>(x, ei, pre, conn, Wt1, y1);
    nonlin_kernel<<<(NN * NCH + 127) / 128, 128>>>(y1, nullptr, h);

    // layer 2
    self_gemm<<<NN / 4, 80>>>(h, Wst2, b2, y2);
    edge_gemm<<<NE / TE, TE, SMEM_EDGE>>>(h, ei, pre, conn, Wt2, y2);

    // residual + final nonlin -> output
    nonlin_kernel<<<(NN * NCH + 127) / 128, 128>>>(y2, x, out);
}

// round 9
// speedup vs baseline: 1.4384x; 1.4384x over previous
#include <cuda_runtime.h>
#include <cuda_bf16.h>
#include <cstdint>

#define NN   10000
#define NE   160000
#define NCH  16
#define CQ   80        // c*5+q
#define OPD  80        // o*5+p  (GEMM N)
#define NFR  10        // f*2+r
#define KTOT 800       // cq*10+fr
#define KC   80        // K per chunk = 8 cq columns = 5 k16 MMA steps
#define NCHUNK 10
#define TEB  128       // edges per block (GEMM M)
#define THR  256
#define RSW  44        // A/B tile row stride in 32-bit words (88 bf16 = 176B, conflict-free)

// ---------------- device scratch (allocation-free) ----------------
__device__ __align__(16) float g_y1[NN * OPD];
__device__ __align__(16) float g_h [NN * OPD];
__device__ __align__(16) float g_y2[NN * OPD];
__device__ __align__(16) float g_Wst1[CQ * OPD];
__device__ __align__(16) float g_Wst2[CQ * OPD];
// W split into bf16 hi/lo, padded-row tiles: [chunk][80 n][88 kk]
#define BCH (80 * 88)
__device__ __align__(16) unsigned short g_Bh1[NCHUNK * BCH];
__device__ __align__(16) unsigned short g_Bl1[NCHUNK * BCH];
__device__ __align__(16) unsigned short g_Bh2[NCHUNK * BCH];
__device__ __align__(16) unsigned short g_Bl2[NCHUNK * BCH];

// ---------------- SMEM map for edge kernel (bytes) ----------------
#define OFF_DST  0          // 128 int = 512
#define OFF_PRE  512        // 128x10 f32 = 5120
#define OFF_XT   5632       // 128x81 f32 = 41472
#define OFF_AH   47104      // 128x44 words = 22528
#define OFF_AL   69632      // 22528
#define OFF_BH   92160      // 80x44 words = 14080
#define OFF_BL   106240     // 14080
#define SMEM_TOT 120320

// mma.sync m16n8k16 bf16 -> f32 (base sm_80+ feature; compiles on compute_103)
static __device__ __forceinline__ void hmma(float* c, const uint32_t* a, const uint32_t* b) {
    asm volatile(
        "mma.sync.aligned.m16n8k16.row.col.f32.bf16.bf16.f32 "
        "{%0,%1,%2,%3}, {%4,%5,%6,%7}, {%8,%9}, {%0,%1,%2,%3};"
        : "+f"(c[0]), "+f"(c[1]), "+f"(c[2]), "+f"(c[3])
        : "r"(a[0]), "r"(a[1]), "r"(a[2]), "r"(a[3]), "r"(b[0]), "r"(b[1]));
}

// ---- prep: Ws relayout + W split into bf16 hi/lo padded B tiles ----
__global__ void prep_weights(const float* __restrict__ W1, const float* __restrict__ W2,
                             const float* __restrict__ Ws1, const float* __restrict__ Ws2) {
    int i = blockIdx.x * blockDim.x + threadIdx.x;
    if (i < NCHUNK * BCH) {
        int c = i / BCH, rem = i % BCH;
        int n = rem / 88, kk = rem % 88;
        float w1 = 0.f, w2 = 0.f;
        if (kk < KC) {
            int k = c * KC + kk;
            int cq = k / 10, fr = k % 10;
            int cc = cq / 5, q = cq % 5, f = fr >> 1, r = fr & 1;
            int o = n / 5, p = n % 5;
            int s = ((((o * NCH + cc) * 5 + p) * 5 + q) * 5 + f) * 2 + r;
            w1 = W1[s]; w2 = W2[s];
        }
        __nv_bfloat16 h1 = __float2bfloat16_rn(w1);
        __nv_bfloat16 l1 = __float2bfloat16_rn(w1 - __bfloat162float(h1));
        __nv_bfloat16 h2 = __float2bfloat16_rn(w2);
        __nv_bfloat16 l2 = __float2bfloat16_rn(w2 - __bfloat162float(h2));
        g_Bh1[i] = __bfloat16_as_ushort(h1);
        g_Bl1[i] = __bfloat16_as_ushort(l1);
        g_Bh2[i] = __bfloat16_as_ushort(h2);
        g_Bl2[i] = __bfloat16_as_ushort(l2);
    }
    if (i < CQ * OPD) {
        int op = i % OPD, cq = i / OPD;
        int o = op / 5, p = op % 5, c = cq / 5, q = cq % 5;
        int src = ((o * NCH + c) * 5 + p) * 5 + q;
        g_Wst1[i] = Ws1[src];
        g_Wst2[i] = Ws2[src];
    }
}

// ---- self-interaction (fp32, initializes y incl. bias) ----
__global__ __launch_bounds__(80) void self_gemm(const float* __restrict__ x,
                                                const float* __restrict__ Wst,
                                                const float* __restrict__ b,
                                                float* __restrict__ y) {
    __shared__ float xs[4][CQ];
    int n0 = blockIdx.x * 4;
    int t = threadIdx.x;
#pragma unroll
    for (int j = 0; j < 4; ++j) xs[j][t] = x[(n0 + j) * CQ + t];
    __syncthreads();
    float bias = ((t % 5) == 0) ? b[t / 5] : 0.f;
    float a0 = bias, a1 = bias, a2 = bias, a3 = bias;
#pragma unroll 8
    for (int k = 0; k < CQ; ++k) {
        float w = __ldg(&Wst[k * OPD + t]);
        a0 = fmaf(xs[0][k], w, a0);
        a1 = fmaf(xs[1][k], w, a1);
        a2 = fmaf(xs[2][k], w, a2);
        a3 = fmaf(xs[3][k], w, a3);
    }
    y[(n0 + 0) * OPD + t] = a0;
    y[(n0 + 1) * OPD + t] = a1;
    y[(n0 + 2) * OPD + t] = a2;
    y[(n0 + 3) * OPD + t] = a3;
}

// ---- HMMA edge GEMM: D[128,80] = V[128,800]*W^T, bf16 3-pass split, fp32 acc ----
__global__ __launch_bounds__(THR, 1) void edge_gemm_tc(
    const float* __restrict__ xin,
    const int*   __restrict__ ei,
    const float* __restrict__ precomp,
    const float* __restrict__ conn,
    const unsigned short* __restrict__ Bgh,
    const unsigned short* __restrict__ Bgl,
    float* __restrict__ y)
{
    extern __shared__ unsigned char smem[];
    int*      dst_s = (int*)(smem + OFF_DST);
    float*    pres  = (float*)(smem + OFF_PRE);   // [128][10]
    float*    xt    = (float*)(smem + OFF_XT);    // [128][81]
    uint32_t* Ah    = (uint32_t*)(smem + OFF_AH); // [128][44] bf16x2 words
    uint32_t* Al    = (uint32_t*)(smem + OFF_AL);
    uint32_t* Bh    = (uint32_t*)(smem + OFF_BH); // [80][44]
    uint32_t* Bl    = (uint32_t*)(smem + OFF_BL);

    const int tid = threadIdx.x;
    const int e    = tid >> 1, half = tid & 1;
    const int eg   = blockIdx.x * TEB + e;

    // ---- phase 1: gather + parallel transport (2 threads per edge) ----
    {
        int src = ei[2 * eg];
        if (!half) dst_s[e] = ei[2 * eg + 1];
        float phi = conn[eg];
        float s1, c1, s2, c2;
        __sincosf(phi, &s1, &c1);
        __sincosf(2.f * phi, &s2, &c2);
        const float4* xr = (const float4*)(xin + (long long)src * CQ);
#pragma unroll
        for (int g = 0; g < 2; ++g) {
            int c4 = 2 * half + g;
            float v[20];
#pragma unroll
            for (int j = 0; j < 5; ++j) {
                float4 t4 = xr[c4 * 5 + j];
                v[4*j] = t4.x; v[4*j+1] = t4.y; v[4*j+2] = t4.z; v[4*j+3] = t4.w;
            }
#pragma unroll
            for (int cc = 0; cc < 4; ++cc) {
                int c = c4 * 4 + cc;
                float m0 = v[cc*5], x1 = v[cc*5+1], x2 = v[cc*5+2], x3 = v[cc*5+3], x4 = v[cc*5+4];
                float* row = xt + e * 81 + c * 5;
                row[0] = m0;
                row[1] = c1 * x1 - s1 * x2;
                row[2] = s1 * x1 + c1 * x2;
                row[3] = c2 * x3 - s2 * x4;
                row[4] = s2 * x3 + c2 * x4;
            }
        }
    }
    for (int i = tid; i < TEB * NFR; i += THR)
        pres[i] = precomp[(long long)blockIdx.x * TEB * NFR + i];
    __syncthreads();

    float pr[NFR];
#pragma unroll
    for (int f = 0; f < NFR; ++f) pr[f] = pres[e * NFR + f];

    // warp tiling: 8 warps = 4 M-tiles(32) x 2 N-tiles(40)
    const int wid = tid >> 5, lid = tid & 31;
    const int wm = wid & 3, wn = wid >> 2;
    const int lg = lid >> 2, lt = lid & 3;     // groupID, tid-in-group

    float acc[2][5][4];
#pragma unroll
    for (int m = 0; m < 2; ++m)
#pragma unroll
        for (int nf = 0; nf < 5; ++nf)
#pragma unroll
            for (int j = 0; j < 4; ++j) acc[m][nf][j] = 0.f;

#pragma unroll 1
    for (int c = 0; c < NCHUNK; ++c) {
        // stage B hi/lo tiles (80 rows x 176B, contiguous in gmem incl. pad)
        {
            const uint4* sh = (const uint4*)(Bgh + c * BCH);
            const uint4* sl = (const uint4*)(Bgl + c * BCH);
            uint4* dh = (uint4*)Bh;
            uint4* dl = (uint4*)Bl;
            for (int i = tid; i < BCH / 8; i += THR) { dh[i] = sh[i]; dl[i] = sl[i]; }
        }
        // build A tile: V[e, kk] = xt[e, 8c + kk/10] * pr[kk%10], bf16 hi/lo
        {
#pragma unroll
            for (int g4 = 0; g4 < 4; ++g4) {
                int cq = 8 * c + half * 4 + g4;
                float xv = xt[e * 81 + cq];
                int wbase = e * RSW + (half * 40 + g4 * 10) / 2;
#pragma unroll
                for (int fr = 0; fr < 10; fr += 2) {
                    float v0 = xv * pr[fr];
                    float v1 = xv * pr[fr + 1];
                    __nv_bfloat16 h0 = __float2bfloat16_rn(v0);
                    __nv_bfloat16 h1 = __float2bfloat16_rn(v1);
                    float l0 = v0 - __bfloat162float(h0);
                    float l1 = v1 - __bfloat162float(h1);
                    uint32_t hp = (uint32_t)__bfloat16_as_ushort(h0) |
                                  ((uint32_t)__bfloat16_as_ushort(h1) << 16);
                    uint32_t lp = (uint32_t)__bfloat16_as_ushort(__float2bfloat16_rn(l0)) |
                                  ((uint32_t)__bfloat16_as_ushort(__float2bfloat16_rn(l1)) << 16);
                    Ah[wbase + fr / 2] = hp;
                    Al[wbase + fr / 2] = lp;
                }
            }
        }
        __syncthreads();

        // MMA: 5 k16-steps, 3 passes (AhBh + AhBl + AlBh)
#pragma unroll
        for (int s = 0; s < 5; ++s) {
            uint32_t afh[2][4], afl[2][4], bfh[5][2], bfl[5][2];
#pragma unroll
            for (int m = 0; m < 2; ++m) {
                int r0 = (wm * 32 + m * 16 + lg) * RSW + s * 8 + lt;
                int r1 = r0 + 8 * RSW;
                afh[m][0] = Ah[r0];     afh[m][1] = Ah[r1];
                afh[m][2] = Ah[r0 + 4]; afh[m][3] = Ah[r1 + 4];
                afl[m][0] = Al[r0];     afl[m][1] = Al[r1];
                afl[m][2] = Al[r0 + 4]; afl[m][3] = Al[r1 + 4];
            }
#pragma unroll
            for (int nf = 0; nf < 5; ++nf) {
                int b0 = (wn * 40 + nf * 8 + lg) * RSW + s * 8 + lt;
                bfh[nf][0] = Bh[b0]; bfh[nf][1] = Bh[b0 + 4];
                bfl[nf][0] = Bl[b0]; bfl[nf][1] = Bl[b0 + 4];
            }
#pragma unroll
            for (int m = 0; m < 2; ++m)
#pragma unroll
                for (int nf = 0; nf < 5; ++nf) {
                    hmma(acc[m][nf], afh[m], bfh[nf]);
                    hmma(acc[m][nf], afh[m], bfl[nf]);
                    hmma(acc[m][nf], afl[m], bfh[nf]);
                }
        }
        __syncthreads();
    }

    // ---- epilogue: scatter C fragments (col pairs are contiguous) ----
#pragma unroll
    for (int m = 0; m < 2; ++m) {
        int r0 = wm * 32 + m * 16 + lg;
        int r1 = r0 + 8;
        long long d0 = dst_s[r0], d1 = dst_s[r1];
#pragma unroll
        for (int nf = 0; nf < 5; ++nf) {
            int col = wn * 40 + nf * 8 + 2 * lt;
            asm volatile("red.global.add.v2.f32 [%0], {%1, %2};"
                         :: "l"(y + d0 * OPD + col), "f"(acc[m][nf][0]), "f"(acc[m][nf][1])
                         : "memory");
            asm volatile("red.global.add.v2.f32 [%0], {%1, %2};"
                         :: "l"(y + d1 * OPD + col), "f"(acc[m][nf][2]), "f"(acc[m][nf][3])
                         : "memory");
        }
    }
}

// ---- Fourier -> samples -> ReLU -> Fourier (K=7, order 2), optional residual ----
__global__ void nonlin_kernel(const float* __restrict__ in,
                              const float* __restrict__ resid,
                              float* __restrict__ out) {
    int i = blockIdx.x * blockDim.x + threadIdx.x;
    if (i >= NN * NCH) return;
    float v0 = in[i*5+0], v1 = in[i*5+1], v2 = in[i*5+2], v3 = in[i*5+3], v4 = in[i*5+4];
    if (resid) {
        v0 += resid[i*5+0]; v1 += resid[i*5+1]; v2 += resid[i*5+2];
        v3 += resid[i*5+3]; v4 += resid[i*5+4];
    }
    float o0 = 0.f, o1 = 0.f, o2 = 0.f, o3 = 0.f, o4 = 0.f;
#pragma unroll
    for (int k = 0; k < 7; ++k) {
        float th = 0.8975979010256552f * (float)k;
        float s1, c1, s2, c2;
        __sincosf(th, &s1, &c1);
        __sincosf(2.f * th, &s2, &c2);
        float s = v0 + c1*v1 + s1*v2 + c2*v3 + s2*v4;
        s = fmaxf(s, 0.f);
        o0 += s; o1 += s*c1; o2 += s*s1; o3 += s*c2; o4 += s*s2;
    }
    out[i*5+0] = o0 * (1.f/7.f);
    out[i*5+1] = o1 * (2.f/7.f);
    out[i*5+2] = o2 * (2.f/7.f);
    out[i*5+3] = o3 * (2.f/7.f);
    out[i*5+4] = o4 * (2.f/7.f);
}

extern "C" void kernel_launch(void* const* d_in, const int* in_sizes, int n_in,
                              void* d_out, int out_size) {
    const float* x    = (const float*)d_in[0];
    const int*   ei   = (const int*)d_in[1];   // int32 (JAX x64 disabled)
    const float* pre  = (const float*)d_in[2];
    const float* conn = (const float*)d_in[3];
    const float* W1   = (const float*)d_in[4];
    const float* b1   = (const float*)d_in[5];
    const float* Ws1  = (const float*)d_in[6];
    const float* W2   = (const float*)d_in[7];
    const float* b2   = (const float*)d_in[8];
    const float* Ws2  = (const float*)d_in[9];
    float* out = (float*)d_out;

    cudaFuncSetAttribute(edge_gemm_tc, cudaFuncAttributeMaxDynamicSharedMemorySize, SMEM_TOT);

    float *y1, *h, *y2, *Wst1, *Wst2;
    unsigned short *Bh1, *Bl1, *Bh2, *Bl2;
    cudaGetSymbolAddress((void**)&y1,   g_y1);
    cudaGetSymbolAddress((void**)&h,    g_h);
    cudaGetSymbolAddress((void**)&y2,   g_y2);
    cudaGetSymbolAddress((void**)&Wst1, g_Wst1);
    cudaGetSymbolAddress((void**)&Wst2, g_Wst2);
    cudaGetSymbolAddress((void**)&Bh1,  g_Bh1);
    cudaGetSymbolAddress((void**)&Bl1,  g_Bl1);
    cudaGetSymbolAddress((void**)&Bh2,  g_Bh2);
    cudaGetSymbolAddress((void**)&Bl2,  g_Bl2);

    prep_weights<<<(NCHUNK * BCH + 255) / 256, 256>>>(W1, W2, Ws1, Ws2);

    // layer 1
    self_gemm<<<NN / 4, 80>>>(x, Wst1, b1, y1);
    edge_gemm_tc<<<NE / TEB, THR, SMEM_TOT>>>(x, ei, pre, conn, Bh1, Bl1, y1);
    nonlin_kernel<<<(NN * NCH + 127) / 128, 128>>>(y1, nullptr, h);

    // layer 2
    self_gemm<<<NN / 4, 80>>>(h, Wst2, b2, y2);
    edge_gemm_tc<<<NE / TEB, THR, SMEM_TOT>>>(h, ei, pre, conn, Bh2, Bl2, y2);

    // residual + final nonlin -> output
    nonlin_kernel<<<(NN * NCH + 127) / 128, 128>>>(y2, x, out);
}

// round 10
// speedup vs baseline: 2.3539x; 1.6365x over previous
#include <cuda_runtime.h>
#include <cuda_bf16.h>
#include <cstdint>

#define NN   10000
#define NE   160000
#define NCH  16
#define CQ   80        // c*5+q  (chunk K dimension after fr-major reorder)
#define OPD  80        // o*5+p  (GEMM N)
#define NFR  10        // f*2+r
#define NCHUNK 10      // chunks = fr values; K = fr*80 + cq
#define TEB  128       // edges per block (GEMM M)
#define THR  256
#define XTS  88        // xt row stride in words (conflict-free LDS.64: 88%32=24)
#define BRS  40        // B row stride in words (80 bf16, zero pad; conflict-free LDS.64)

// ---------------- device scratch (allocation-free) ----------------
__device__ __align__(16) float g_y1[NN * OPD];
__device__ __align__(16) float g_h [NN * OPD];
__device__ __align__(16) float g_y2[NN * OPD];
__device__ __align__(16) float g_Wst1[CQ * OPD];
__device__ __align__(16) float g_Wst2[CQ * OPD];
// W bf16 hi/lo, fr-major chunks, word-interleaved rows: [chunk][80 n][80 kk]
#define BCH (80 * 80)   // halfwords per chunk
__device__ __align__(16) unsigned short g_Bh1[NCHUNK * BCH];
__device__ __align__(16) unsigned short g_Bl1[NCHUNK * BCH];
__device__ __align__(16) unsigned short g_Bh2[NCHUNK * BCH];
__device__ __align__(16) unsigned short g_Bl2[NCHUNK * BCH];

// ---------------- SMEM map (bytes) ----------------
#define OFF_DST  0          // 128 int
#define OFF_PRE  512        // 128x10 f32 = 5120
#define OFF_XT   5632       // 128x88 words = 45056
#define OFF_BH   50688      // 80x40 words = 12800
#define OFF_BL   63488      // 12800
#define SMEM_TOT 76288

// mma.sync m16n8k16 bf16 -> f32 (base feature, compiles on compute_103)
static __device__ __forceinline__ void hmma(float* c, const uint32_t* a, const uint32_t* b) {
    asm volatile(
        "mma.sync.aligned.m16n8k16.row.col.f32.bf16.bf16.f32 "
        "{%0,%1,%2,%3}, {%4,%5,%6,%7}, {%8,%9}, {%0,%1,%2,%3};"
        : "+f"(c[0]), "+f"(c[1]), "+f"(c[2]), "+f"(c[3])
        : "r"(a[0]), "r"(a[1]), "r"(a[2]), "r"(a[3]), "r"(b[0]), "r"(b[1]));
}
// pack bf16x2 from two f32 by truncation (hi parts)
static __device__ __forceinline__ uint32_t pack_hi(float v0, float v1) {
    return __byte_perm(__float_as_uint(v0), __float_as_uint(v1), 0x7632);
}
static __device__ __forceinline__ uint32_t pack_lo(float v0, float v1) {
    float h0 = __uint_as_float(__float_as_uint(v0) & 0xFFFF0000u);
    float h1 = __uint_as_float(__float_as_uint(v1) & 0xFFFF0000u);
    float l0 = v0 - h0, l1 = v1 - h1;
    uint32_t r;
    asm("cvt.rn.bf16x2.f32 %0, %1, %2;" : "=r"(r) : "f"(l1), "f"(l0));
    return r;
}

// ---- prep: Ws relayout + W split bf16 hi/lo, fr-major, word-interleaved ----
__global__ void prep_weights(const float* __restrict__ W1, const float* __restrict__ W2,
                             const float* __restrict__ Ws1, const float* __restrict__ Ws2) {
    int i = blockIdx.x * blockDim.x + threadIdx.x;
    if (i < NCHUNK * BCH) {
        int c = i / BCH, rem = i % BCH;
        int n = rem / CQ, kk = rem % CQ;        // kk = cq
        int f = c >> 1, r = c & 1;
        int cc = kk / 5, q = kk % 5;
        int o = n / 5, p = n % 5;
        int src = ((((o * NCH + cc) * 5 + p) * 5 + q) * 5 + f) * 2 + r;
        float w1 = W1[src], w2 = W2[src];
        // word interleave within each 16-k step group so (b0,b1) is LDS.64:
        // old word w (0..7) -> new: w<4 ? 2w : 2(w-4)+1
        int s = kk / 16, j = kk % 16;
        int wo = j >> 1, par = j & 1;
        int wn2 = (wo < 4) ? (2 * wo) : (2 * (wo - 4) + 1);
        int hidx = (c * 80 + n) * CQ + s * 16 + wn2 * 2 + par;
        __nv_bfloat16 h1 = __float2bfloat16_rn(w1);
        __nv_bfloat16 l1 = __float2bfloat16_rn(w1 - __bfloat162float(h1));
        __nv_bfloat16 h2 = __float2bfloat16_rn(w2);
        __nv_bfloat16 l2 = __float2bfloat16_rn(w2 - __bfloat162float(h2));
        g_Bh1[hidx] = __bfloat16_as_ushort(h1);
        g_Bl1[hidx] = __bfloat16_as_ushort(l1);
        g_Bh2[hidx] = __bfloat16_as_ushort(h2);
        g_Bl2[hidx] = __bfloat16_as_ushort(l2);
    }
    if (i < CQ * OPD) {
        int op = i % OPD, cq = i / OPD;
        int o = op / 5, p = op % 5, c = cq / 5, q = cq % 5;
        int src = ((o * NCH + c) * 5 + p) * 5 + q;
        g_Wst1[i] = Ws1[src];
        g_Wst2[i] = Ws2[src];
    }
}

// ---- self-interaction (fp32, initializes y incl. bias) ----
__global__ __launch_bounds__(80) void self_gemm(const float* __restrict__ x,
                                                const float* __restrict__ Wst,
                                                const float* __restrict__ b,
                                                float* __restrict__ y) {
    __shared__ float xs[4][CQ];
    int n0 = blockIdx.x * 4;
    int t = threadIdx.x;
#pragma unroll
    for (int j = 0; j < 4; ++j) xs[j][t] = x[(n0 + j) * CQ + t];
    __syncthreads();
    float bias = ((t % 5) == 0) ? b[t / 5] : 0.f;
    float a0 = bias, a1 = bias, a2 = bias, a3 = bias;
#pragma unroll 8
    for (int k = 0; k < CQ; ++k) {
        float w = __ldg(&Wst[k * OPD + t]);
        a0 = fmaf(xs[0][k], w, a0);
        a1 = fmaf(xs[1][k], w, a1);
        a2 = fmaf(xs[2][k], w, a2);
        a3 = fmaf(xs[3][k], w, a3);
    }
    y[(n0 + 0) * OPD + t] = a0;
    y[(n0 + 1) * OPD + t] = a1;
    y[(n0 + 2) * OPD + t] = a2;
    y[(n0 + 3) * OPD + t] = a3;
}

// ---- HMMA edge GEMM: A fragments built in registers (fr-major chunks) ----
__global__ __launch_bounds__(THR, 2) void edge_gemm_tc(
    const float* __restrict__ xin,
    const int*   __restrict__ ei,
    const float* __restrict__ precomp,
    const float* __restrict__ conn,
    const unsigned short* __restrict__ Bgh,
    const unsigned short* __restrict__ Bgl,
    float* __restrict__ y)
{
    extern __shared__ unsigned char smem[];
    int*      dst_s = (int*)(smem + OFF_DST);
    float*    pres  = (float*)(smem + OFF_PRE);   // [128][10]
    float*    xt    = (float*)(smem + OFF_XT);    // [128][88]
    uint32_t* Bh    = (uint32_t*)(smem + OFF_BH); // [80][40]
    uint32_t* Bl    = (uint32_t*)(smem + OFF_BL);

    const int tid = threadIdx.x;
    const int e    = tid >> 1, half = tid & 1;
    const int eg   = blockIdx.x * TEB + e;

    // ---- phase 1: gather + parallel transport (2 threads per edge) ----
    {
        int src = ei[2 * eg];
        if (!half) dst_s[e] = ei[2 * eg + 1];
        float phi = conn[eg];
        float s1, c1, s2, c2;
        __sincosf(phi, &s1, &c1);
        __sincosf(2.f * phi, &s2, &c2);
        const float4* xr = (const float4*)(xin + (long long)src * CQ);
#pragma unroll
        for (int g = 0; g < 2; ++g) {
            int c4 = 2 * half + g;
            float v[20];
#pragma unroll
            for (int j = 0; j < 5; ++j) {
                float4 t4 = xr[c4 * 5 + j];
                v[4*j] = t4.x; v[4*j+1] = t4.y; v[4*j+2] = t4.z; v[4*j+3] = t4.w;
            }
#pragma unroll
            for (int cc = 0; cc < 4; ++cc) {
                int c = c4 * 4 + cc;
                float m0 = v[cc*5], x1 = v[cc*5+1], x2 = v[cc*5+2], x3 = v[cc*5+3], x4 = v[cc*5+4];
                float* row = xt + e * XTS + c * 5;
                row[0] = m0;
                row[1] = c1 * x1 - s1 * x2;
                row[2] = s1 * x1 + c1 * x2;
                row[3] = c2 * x3 - s2 * x4;
                row[4] = s2 * x3 + c2 * x4;
            }
        }
    }
    for (int i = tid; i < TEB * NFR; i += THR)
        pres[i] = precomp[(long long)blockIdx.x * TEB * NFR + i];
    __syncthreads();

    // warp tiling: 8 warps = 4 M-tiles(32) x 2 N-tiles(40)
    const int wid = tid >> 5, lid = tid & 31;
    const int wm = wid & 3, wn = wid >> 2;
    const int lg = lid >> 2, lt = lid & 3;

    int rr[4];
#pragma unroll
    for (int i = 0; i < 4; ++i) rr[i] = wm * 32 + 8 * i + lg;   // A rows owned

    float acc[2][5][4];
#pragma unroll
    for (int m = 0; m < 2; ++m)
#pragma unroll
        for (int nf = 0; nf < 5; ++nf)
#pragma unroll
            for (int j = 0; j < 4; ++j) acc[m][nf][j] = 0.f;

#pragma unroll 1
    for (int c = 0; c < NCHUNK; ++c) {
        if (c) __syncthreads();   // protect B buffer from overwrite
        // stage B hi/lo chunk (12800B each, contiguous)
        {
            const uint4* sh = (const uint4*)(Bgh + c * BCH);
            const uint4* sl = (const uint4*)(Bgl + c * BCH);
            uint4* dh = (uint4*)Bh;
            uint4* dl = (uint4*)Bl;
#pragma unroll
            for (int i = 0; i < 4; ++i) {
                int idx = tid + i * THR;
                if (idx < 800) { dh[idx] = sh[idx]; dl[idx] = sl[idx]; }
            }
        }
        float prr[4];
#pragma unroll
        for (int i = 0; i < 4; ++i) prr[i] = pres[rr[i] * NFR + c];
        __syncthreads();

#pragma unroll
        for (int s = 0; s < 5; ++s) {
            const int ko = 16 * s + 2 * lt;
            // B fragments: one LDS.64 per (nf, h/l) thanks to word interleave
            uint32_t bh[5][2], bl[5][2];
#pragma unroll
            for (int nf = 0; nf < 5; ++nf) {
                int bw = (wn * 40 + nf * 8 + lg) * BRS + s * 8 + 2 * lt;
                uint2 th = *(const uint2*)&Bh[bw];
                uint2 tl = *(const uint2*)&Bl[bw];
                bh[nf][0] = th.x; bh[nf][1] = th.y;
                bl[nf][0] = tl.x; bl[nf][1] = tl.y;
            }
            // A fragments built in registers: V = pr[row] * xt[row][k]
            uint32_t ah[2][4], al[2][4];
#pragma unroll
            for (int m = 0; m < 2; ++m) {
#pragma unroll
                for (int i2 = 0; i2 < 2; ++i2) {
                    const float* xrow = xt + rr[2 * m + i2] * XTS;
                    float p = prr[2 * m + i2];
                    float2 x0 = *(const float2*)&xrow[ko];       // k lo pair
                    float2 x1 = *(const float2*)&xrow[ko + 8];   // k hi pair
                    float v00 = x0.x * p, v01 = x0.y * p;
                    float v10 = x1.x * p, v11 = x1.y * p;
                    ah[m][i2]     = pack_hi(v00, v01);
                    ah[m][i2 + 2] = pack_hi(v10, v11);
                    al[m][i2]     = pack_lo(v00, v01);
                    al[m][i2 + 2] = pack_lo(v10, v11);
                }
            }
#pragma unroll
            for (int m = 0; m < 2; ++m)
#pragma unroll
                for (int nf = 0; nf < 5; ++nf) {
                    hmma(acc[m][nf], ah[m], bh[nf]);
                    hmma(acc[m][nf], ah[m], bl[nf]);
                    hmma(acc[m][nf], al[m], bh[nf]);
                }
        }
    }

    // ---- epilogue: scatter C fragments (col pairs contiguous) ----
#pragma unroll
    for (int m = 0; m < 2; ++m) {
        int r0 = wm * 32 + m * 16 + lg;
        int r1 = r0 + 8;
        long long d0 = dst_s[r0], d1 = dst_s[r1];
#pragma unroll
        for (int nf = 0; nf < 5; ++nf) {
            int col = wn * 40 + nf * 8 + 2 * lt;
            asm volatile("red.global.add.v2.f32 [%0], {%1, %2};"
                         :: "l"(y + d0 * OPD + col), "f"(acc[m][nf][0]), "f"(acc[m][nf][1])
                         : "memory");
            asm volatile("red.global.add.v2.f32 [%0], {%1, %2};"
                         :: "l"(y + d1 * OPD + col), "f"(acc[m][nf][2]), "f"(acc[m][nf][3])
                         : "memory");
        }
    }
}

// ---- Fourier -> samples -> ReLU -> Fourier (K=7, order 2), optional residual ----
__global__ void nonlin_kernel(const float* __restrict__ in,
                              const float* __restrict__ resid,
                              float* __restrict__ out) {
    int i = blockIdx.x * blockDim.x + threadIdx.x;
    if (i >= NN * NCH) return;
    float v0 = in[i*5+0], v1 = in[i*5+1], v2 = in[i*5+2], v3 = in[i*5+3], v4 = in[i*5+4];
    if (resid) {
        v0 += resid[i*5+0]; v1 += resid[i*5+1]; v2 += resid[i*5+2];
        v3 += resid[i*5+3]; v4 += resid[i*5+4];
    }
    float o0 = 0.f, o1 = 0.f, o2 = 0.f, o3 = 0.f, o4 = 0.f;
#pragma unroll
    for (int k = 0; k < 7; ++k) {
        float th = 0.8975979010256552f * (float)k;
        float s1, c1, s2, c2;
        __sincosf(th, &s1, &c1);
        __sincosf(2.f * th, &s2, &c2);
        float s = v0 + c1*v1 + s1*v2 + c2*v3 + s2*v4;
        s = fmaxf(s, 0.f);
        o0 += s; o1 += s*c1; o2 += s*s1; o3 += s*c2; o4 += s*s2;
    }
    out[i*5+0] = o0 * (1.f/7.f);
    out[i*5+1] = o1 * (2.f/7.f);
    out[i*5+2] = o2 * (2.f/7.f);
    out[i*5+3] = o3 * (2.f/7.f);
    out[i*5+4] = o4 * (2.f/7.f);
}

extern "C" void kernel_launch(void* const* d_in, const int* in_sizes, int n_in,
                              void* d_out, int out_size) {
    const float* x    = (const float*)d_in[0];
    const int*   ei   = (const int*)d_in[1];   // int32 (JAX x64 disabled)
    const float* pre  = (const float*)d_in[2];
    const float* conn = (const float*)d_in[3];
    const float* W1   = (const float*)d_in[4];
    const float* b1   = (const float*)d_in[5];
    const float* Ws1  = (const float*)d_in[6];
    const float* W2   = (const float*)d_in[7];
    const float* b2   = (const float*)d_in[8];
    const float* Ws2  = (const float*)d_in[9];
    float* out = (float*)d_out;

    cudaFuncSetAttribute(edge_gemm_tc, cudaFuncAttributeMaxDynamicSharedMemorySize, SMEM_TOT);

    float *y1, *h, *y2, *Wst1, *Wst2;
    unsigned short *Bh1, *Bl1, *Bh2, *Bl2;
    cudaGetSymbolAddress((void**)&y1,   g_y1);
    cudaGetSymbolAddress((void**)&h,    g_h);
    cudaGetSymbolAddress((void**)&y2,   g_y2);
    cudaGetSymbolAddress((void**)&Wst1, g_Wst1);
    cudaGetSymbolAddress((void**)&Wst2, g_Wst2);
    cudaGetSymbolAddress((void**)&Bh1,  g_Bh1);
    cudaGetSymbolAddress((void**)&Bl1,  g_Bl1);
    cudaGetSymbolAddress((void**)&Bh2,  g_Bh2);
    cudaGetSymbolAddress((void**)&Bl2,  g_Bl2);

    prep_weights<<<(NCHUNK * BCH + 255) / 256, 256>>>(W1, W2, Ws1, Ws2);

    // layer 1
    self_gemm<<<NN / 4, 80>>>(x, Wst1, b1, y1);
    edge_gemm_tc<<<NE / TEB, THR, SMEM_TOT>>>(x, ei, pre, conn, Bh1, Bl1, y1);
    nonlin_kernel<<<(NN * NCH + 127) / 128, 128>>>(y1, nullptr, h);

    // layer 2
    self_gemm<<<NN / 4, 80>>>(h, Wst2, b2, y2);
    edge_gemm_tc<<<NE / TEB, THR, SMEM_TOT>>>(h, ei, pre, conn, Bh2, Bl2, y2);

    // residual + final nonlin -> output
    nonlin_kernel<<<(NN * NCH + 127) / 128, 128>>>(y2, x, out);
}